// round 2
// baseline (speedup 1.0000x reference)
#include <cuda_runtime.h>
#include <math.h>

#define BQ 65536
#define NN 100000
#define KH 20
#define HD 128
#define INV_SQRT_H 0.08838834764831845f

// ---------------- scratch (device globals; no allocation allowed) ----------------
__device__ float g_w2t[HD * HD];            // W2 transposed: [d][h] = W2[h][d]
__device__ float g_wq[NN * HD];             // per-node W2 q
__device__ float g_zpart[2 * BQ * HD];      // sum_k a_k (neigh_e + sign_e)
__device__ float g_hbar[2 * BQ * HD];       // sum_k a_k h_k
__device__ float g_zfull[2 * BQ * HD];      // zpart + hbar@W2 + b2

// ---------------- kernel 0: transpose tp_w2 ----------------
__global__ void transpose128_kernel(const float* __restrict__ W) {
    int d = blockIdx.x, h = threadIdx.x;
    g_w2t[d * HD + h] = W[h * HD + d];
}

// ---------------- shared GEMM core: C[M,128] = A[M,128] @ B[128,128] ----------------
// block: 256 threads, tile 64(M) x 128(N), k-chunks of 64.
// thread (mt=tid>>5, nt=tid&31) owns rows mt*8..+7, cols nt*4..+3.
__device__ __forceinline__ void gemm128_core(
    const float* __restrict__ A, const float* __restrict__ Bm, int M,
    float* As, float* Bs, float4 acc[8])
{
    int tid = threadIdx.x;
    int nt = tid & 31, mt = tid >> 5;
    int m0 = blockIdx.x * 64;

    for (int k0 = 0; k0 < 128; k0 += 64) {
        // stage A tile [64 rows][64 k] (row-major, broadcast-read later)
        #pragma unroll
        for (int t = 0; t < 4; t++) {
            int idx = tid + t * 256;
            int row = idx >> 4;
            int kq  = (idx & 15) << 2;
            float4 v = make_float4(0.f, 0.f, 0.f, 0.f);
            if (m0 + row < M)
                v = *(const float4*)(A + (size_t)(m0 + row) * HD + k0 + kq);
            *(float4*)(As + row * 64 + kq) = v;
        }
        // stage B tile [64 k][128 n]
        #pragma unroll
        for (int t = 0; t < 8; t++) {
            int idx = tid + t * 256;
            int row = idx >> 5;
            int nq  = (idx & 31) << 2;
            *(float4*)(Bs + row * HD + nq) =
                *(const float4*)(Bm + (size_t)(k0 + row) * HD + nq);
        }
        __syncthreads();

        #pragma unroll
        for (int k4 = 0; k4 < 16; k4++) {
            float4 b0 = *(float4*)(Bs + (k4 * 4 + 0) * HD + nt * 4);
            float4 b1 = *(float4*)(Bs + (k4 * 4 + 1) * HD + nt * 4);
            float4 b2 = *(float4*)(Bs + (k4 * 4 + 2) * HD + nt * 4);
            float4 b3 = *(float4*)(Bs + (k4 * 4 + 3) * HD + nt * 4);
            #pragma unroll
            for (int r = 0; r < 8; r++) {
                float4 a = *(float4*)(As + (mt * 8 + r) * 64 + k4 * 4);
                acc[r].x += a.x * b0.x + a.y * b1.x + a.z * b2.x + a.w * b3.x;
                acc[r].y += a.x * b0.y + a.y * b1.y + a.z * b2.y + a.w * b3.y;
                acc[r].z += a.x * b0.z + a.y * b1.z + a.z * b2.z + a.w * b3.z;
                acc[r].w += a.x * b0.w + a.y * b1.w + a.z * b2.w + a.w * b3.w;
            }
        }
        __syncthreads();
    }
}

// ---------------- kernel 1: g_wq = node_emb @ W2^T ----------------
__global__ __launch_bounds__(256) void gemm_wq_kernel(const float* __restrict__ node_emb) {
    __shared__ float As[64 * 64];
    __shared__ float Bs[64 * 128];
    float4 acc[8];
    #pragma unroll
    for (int r = 0; r < 8; r++) acc[r] = make_float4(0.f, 0.f, 0.f, 0.f);
    gemm128_core(node_emb, g_w2t, NN, As, Bs, acc);

    int tid = threadIdx.x;
    int nt = tid & 31, mt = tid >> 5;
    int m0 = blockIdx.x * 64;
    #pragma unroll
    for (int r = 0; r < 8; r++) {
        int row = m0 + mt * 8 + r;
        if (row < NN)
            *(float4*)(g_wq + (size_t)row * HD + nt * 4) = acc[r];
    }
}

// ---------------- kernel 3: g_zfull = g_hbar @ W2 + g_zpart + b2 ----------------
__global__ __launch_bounds__(256) void gemm_ztime_kernel(const float* __restrict__ tp_w2,
                                                         const float* __restrict__ tp_b2) {
    __shared__ float As[64 * 64];
    __shared__ float Bs[64 * 128];
    float4 acc[8];
    #pragma unroll
    for (int r = 0; r < 8; r++) acc[r] = make_float4(0.f, 0.f, 0.f, 0.f);
    gemm128_core(g_hbar, tp_w2, 2 * BQ, As, Bs, acc);

    int tid = threadIdx.x;
    int nt = tid & 31, mt = tid >> 5;
    int m0 = blockIdx.x * 64;
    float4 bb = *(const float4*)(tp_b2 + nt * 4);
    #pragma unroll
    for (int r = 0; r < 8; r++) {
        int row = m0 + mt * 8 + r;
        float4 z = *(const float4*)(g_zpart + (size_t)row * HD + nt * 4);
        float4 c = acc[r];
        c.x += z.x + bb.x; c.y += z.y + bb.y; c.z += z.z + bb.z; c.w += z.w + bb.w;
        *(float4*)(g_zfull + (size_t)row * HD + nt * 4) = c;
    }
}

// ---------------- kernel 2: attention (warp per edge-side) ----------------
__device__ __forceinline__ float warp_sum(float v) {
    #pragma unroll
    for (int off = 16; off; off >>= 1) v += __shfl_xor_sync(0xffffffffu, v, off);
    return v;
}

__global__ __launch_bounds__(128) void attn_kernel(
    const int* __restrict__ edge_index, const int* __restrict__ edge_ts,
    const int* __restrict__ h_nb, const int* __restrict__ h_tm, const int* __restrict__ h_sg,
    const float* __restrict__ node_emb, const float* __restrict__ sign_emb,
    const float* __restrict__ tp_w1, const float* __restrict__ tp_b1,
    const float* __restrict__ tp_b2)
{
    int wid  = blockIdx.x * 4 + (threadIdx.x >> 5);   // edge-side id in [0, 2B)
    int lane = threadIdx.x & 31;
    int e    = wid & (BQ - 1);
    int side = wid >> 16;
    int node = edge_index[side * BQ + e];
    int qt   = edge_ts[e];

    const float4* ne4 = (const float4*)node_emb;
    float4 q   = ne4[(size_t)node * 32 + lane];
    float4 wq  = ((const float4*)g_wq)[(size_t)node * 32 + lane];
    float4 w1  = ((const float4*)tp_w1)[lane];
    float4 b1  = ((const float4*)tp_b1)[lane];
    float4 s0  = ((const float4*)sign_emb)[lane];
    float4 s1  = ((const float4*)sign_emb)[32 + lane];
    float4 b2v = ((const float4*)tp_b2)[lane];

    float qs0 = warp_sum(q.x * s0.x + q.y * s0.y + q.z * s0.z + q.w * s0.w);
    float qs1 = warp_sum(q.x * s1.x + q.y * s1.y + q.z * s1.z + q.w * s1.w);
    float qb2 = warp_sum(q.x * b2v.x + q.y * b2v.y + q.z * b2v.z + q.w * b2v.w);

    // lanes 0..19 preload this node's history row; broadcast via shfl
    int nb_l = 0, tm_l = 0, sg_l = 0;
    if (lane < KH) {
        nb_l = h_nb[(size_t)node * KH + lane];
        tm_l = h_tm[(size_t)node * KH + lane];
        sg_l = h_sg[(size_t)node * KH + lane];
    }

    float4 nek[KH];
    float  deltas[KH];
    float  scores[KH];
    unsigned sgm = 0;

    #pragma unroll
    for (int k = 0; k < KH; k++) {
        int nb = __shfl_sync(0xffffffffu, nb_l, k);
        int tm = __shfl_sync(0xffffffffu, tm_l, k);
        int sg = __shfl_sync(0xffffffffu, sg_l, k);
        int nbc = (nb == -1) ? 0 : nb;
        float4 ne = ne4[(size_t)nbc * 32 + lane];
        nek[k] = ne;
        float delta = (float)qt - (float)tm;
        deltas[k] = delta;
        sgm |= (unsigned)(sg & 1) << k;
        float hx = fmaxf(fmaf(delta, w1.x, b1.x), 0.f);
        float hy = fmaxf(fmaf(delta, w1.y, b1.y), 0.f);
        float hz = fmaxf(fmaf(delta, w1.z, b1.z), 0.f);
        float hw = fmaxf(fmaf(delta, w1.w, b1.w), 0.f);
        float p = q.x * ne.x + q.y * ne.y + q.z * ne.z + q.w * ne.w
                + hx * wq.x + hy * wq.y + hz * wq.z + hw * wq.w;
        p = warp_sum(p);
        bool valid = (nb != -1) && (tm < qt);
        float sc = (p + (sg ? qs1 : qs0) + qb2) * INV_SQRT_H;
        scores[k] = valid ? sc : -1e9f;
    }

    float mx = scores[0];
    #pragma unroll
    for (int k = 1; k < KH; k++) mx = fmaxf(mx, scores[k]);
    float sum = 0.f;
    #pragma unroll
    for (int k = 0; k < KH; k++) { scores[k] = __expf(scores[k] - mx); sum += scores[k]; }
    float inv = 1.f / sum;

    float4 z  = make_float4(0.f, 0.f, 0.f, 0.f);
    float4 hb = make_float4(0.f, 0.f, 0.f, 0.f);
    #pragma unroll
    for (int k = 0; k < KH; k++) {
        float a = scores[k] * inv;
        float4 se = ((sgm >> k) & 1u) ? s1 : s0;
        z.x += a * (nek[k].x + se.x);
        z.y += a * (nek[k].y + se.y);
        z.z += a * (nek[k].z + se.z);
        z.w += a * (nek[k].w + se.w);
        float d = deltas[k];
        hb.x += a * fmaxf(fmaf(d, w1.x, b1.x), 0.f);
        hb.y += a * fmaxf(fmaf(d, w1.y, b1.y), 0.f);
        hb.z += a * fmaxf(fmaf(d, w1.z, b1.z), 0.f);
        hb.w += a * fmaxf(fmaf(d, w1.w, b1.w), 0.f);
    }
    ((float4*)g_zpart)[(size_t)wid * 32 + lane] = z;
    ((float4*)g_hbar )[(size_t)wid * 32 + lane] = hb;
}

// ---------------- kernel 4: feat build + classifier GEMM + epilogue ----------------
// out[e] = relu(feat[e] @ em_w1 + em_b1) . em_w2 + em_b2
// feat[e] = [zu, zv, |zu-zv|, zu*zv], zu = g_zfull[e], zv = g_zfull[B+e]
__global__ __launch_bounds__(256) void classifier_kernel(
    const float* __restrict__ em_w1, const float* __restrict__ em_b1,
    const float* __restrict__ em_w2, const float* __restrict__ em_b2,
    float* __restrict__ out)
{
    __shared__ float As[64 * 64];
    __shared__ float Bs[64 * 128];
    int tid = threadIdx.x;
    int nt = tid & 31, mt = tid >> 5;
    int e0 = blockIdx.x * 64;
    const float4* Z4 = (const float4*)g_zfull;

    float4 acc[8];
    #pragma unroll
    for (int r = 0; r < 8; r++) acc[r] = make_float4(0.f, 0.f, 0.f, 0.f);

    for (int c = 0; c < 8; c++) {
        int k0  = c * 64;
        int sel = k0 >> 7;
        int j0  = k0 & 127;
        // stage feat tile [64 rows][64 k]
        #pragma unroll
        for (int t = 0; t < 4; t++) {
            int idx = tid + t * 256;
            int row = idx >> 4;
            int kq  = (idx & 15) << 2;
            int j   = j0 + kq;
            int e   = e0 + row;
            float4 zu = Z4[(size_t)e * 32 + (j >> 2)];
            float4 zv = Z4[(size_t)(BQ + e) * 32 + (j >> 2)];
            float4 v;
            if      (sel == 0) v = zu;
            else if (sel == 1) v = zv;
            else if (sel == 2) v = make_float4(fabsf(zu.x - zv.x), fabsf(zu.y - zv.y),
                                               fabsf(zu.z - zv.z), fabsf(zu.w - zv.w));
            else               v = make_float4(zu.x * zv.x, zu.y * zv.y,
                                               zu.z * zv.z, zu.w * zv.w);
            *(float4*)(As + row * 64 + kq) = v;
        }
        // stage em_w1 rows k0..k0+63
        #pragma unroll
        for (int t = 0; t < 8; t++) {
            int idx = tid + t * 256;
            int row = idx >> 5;
            int nq  = (idx & 31) << 2;
            *(float4*)(Bs + row * HD + nq) =
                *(const float4*)(em_w1 + (size_t)(k0 + row) * HD + nq);
        }
        __syncthreads();

        #pragma unroll
        for (int k4 = 0; k4 < 16; k4++) {
            float4 b0 = *(float4*)(Bs + (k4 * 4 + 0) * HD + nt * 4);
            float4 b1 = *(float4*)(Bs + (k4 * 4 + 1) * HD + nt * 4);
            float4 b2 = *(float4*)(Bs + (k4 * 4 + 2) * HD + nt * 4);
            float4 b3 = *(float4*)(Bs + (k4 * 4 + 3) * HD + nt * 4);
            #pragma unroll
            for (int r = 0; r < 8; r++) {
                float4 a = *(float4*)(As + (mt * 8 + r) * 64 + k4 * 4);
                acc[r].x += a.x * b0.x + a.y * b1.x + a.z * b2.x + a.w * b3.x;
                acc[r].y += a.x * b0.y + a.y * b1.y + a.z * b2.y + a.w * b3.y;
                acc[r].z += a.x * b0.z + a.y * b1.z + a.z * b2.z + a.w * b3.z;
                acc[r].w += a.x * b0.w + a.y * b1.w + a.z * b2.w + a.w * b3.w;
            }
        }
        __syncthreads();
    }

    // epilogue: relu + dot with em_w2, warp-reduce per row
    float4 b1e = *(const float4*)(em_b1 + nt * 4);
    float4 w2e = *(const float4*)(em_w2 + nt * 4);
    float  eb2 = em_b2[0];
    #pragma unroll
    for (int r = 0; r < 8; r++) {
        float p = fmaxf(acc[r].x + b1e.x, 0.f) * w2e.x
                + fmaxf(acc[r].y + b1e.y, 0.f) * w2e.y
                + fmaxf(acc[r].z + b1e.z, 0.f) * w2e.z
                + fmaxf(acc[r].w + b1e.w, 0.f) * w2e.w;
        p = warp_sum(p);
        if (nt == 0) out[e0 + mt * 8 + r] = p + eb2;
    }
}

// ---------------- launch ----------------
extern "C" void kernel_launch(void* const* d_in, const int* in_sizes, int n_in,
                              void* d_out, int out_size) {
    const int*   edge_index = (const int*)d_in[0];
    const int*   edge_ts    = (const int*)d_in[1];
    const int*   h_nb       = (const int*)d_in[2];
    const int*   h_tm       = (const int*)d_in[3];
    const int*   h_sg       = (const int*)d_in[4];
    const float* node_emb   = (const float*)d_in[5];
    const float* sign_emb   = (const float*)d_in[6];
    const float* tp_w1      = (const float*)d_in[7];
    const float* tp_b1      = (const float*)d_in[8];
    const float* tp_w2      = (const float*)d_in[9];
    const float* tp_b2      = (const float*)d_in[10];
    const float* em_w1      = (const float*)d_in[11];
    const float* em_b1      = (const float*)d_in[12];
    const float* em_w2      = (const float*)d_in[13];
    const float* em_b2      = (const float*)d_in[14];
    float* out = (float*)d_out;

    transpose128_kernel<<<HD, HD>>>(tp_w2);
    gemm_wq_kernel<<<(NN + 63) / 64, 256>>>(node_emb);
    attn_kernel<<<(2 * BQ) / 4, 128>>>(edge_index, edge_ts, h_nb, h_tm, h_sg,
                                       node_emb, sign_emb, tp_w1, tp_b1, tp_b2);
    gemm_ztime_kernel<<<(2 * BQ) / 64, 256>>>(tp_w2, tp_b2);
    classifier_kernel<<<BQ / 64, 256>>>(em_w1, em_b1, em_w2, em_b2, out);
}